// round 4
// baseline (speedup 1.0000x reference)
#include <cuda_runtime.h>
#include <cstdint>
#include <cstddef>

#define BATCH   16
#define LSEQ    4096
#define INDIM   64
#define DMODEL  128
#define OUTDIM  64
#define TCHUNK  128
#define NCHUNK  32          // LSEQ / TCHUNK
#define CHAINS  256         // 128 p * {re,im}

// ---------------- device scratch (no allocations allowed) ----------------
__device__ float  g_w[(size_t)BATCH * LSEQ * CHAINS];        // local-scan w (67MB)
__device__ float2 g_carry[BATCH * NCHUNK * CHAINS];          // chunk-local final states
__device__ float2 g_cin[BATCH * NCHUNK * CHAINS];            // exclusive cross-chunk prefix
__device__ float  g_BW[CHAINS * INDIM];                      // fused B_part * W_in
__device__ float  g_BuC[CHAINS];                             // B_part * b_in
__device__ float4 g_Pm[TCHUNK * DMODEL];                     // M^{j+1} per p: {m11,m12,m21,m22}
__device__ float  g_WcT[320 * OUTDIM];                       // fused output matrix, [k][o]
__device__ float  g_bias[OUTDIM];

// ---------------- f32x2 / smem helpers ----------------
__device__ __forceinline__ unsigned long long pack2(float lo, float hi) {
    unsigned long long r;
    asm("mov.b64 %0, {%1, %2};" : "=l"(r) : "f"(lo), "f"(hi));
    return r;
}
__device__ __forceinline__ float2 unpack2(unsigned long long v) {
    float lo, hi;
    asm("mov.b64 {%0, %1}, %2;" : "=f"(lo), "=f"(hi) : "l"(v));
    return make_float2(lo, hi);
}
__device__ __forceinline__ unsigned long long fma2(unsigned long long a, unsigned long long b, unsigned long long c) {
    unsigned long long d;
    asm("fma.rn.f32x2 %0, %1, %2, %3;" : "=l"(d) : "l"(a), "l"(b), "l"(c));
    return d;
}
__device__ __forceinline__ unsigned long long add2(unsigned long long a, unsigned long long b) {
    unsigned long long d;
    asm("add.rn.f32x2 %0, %1, %2;" : "=l"(d) : "l"(a), "l"(b));
    return d;
}
__device__ __forceinline__ void lds_v2u64(unsigned long long &a, unsigned long long &b, uint32_t addr) {
    asm volatile("ld.shared.v2.u64 {%0, %1}, [%2];" : "=l"(a), "=l"(b) : "r"(addr));
}
__device__ __forceinline__ void sts_u64(uint32_t addr, unsigned long long v) {
    asm volatile("st.shared.b64 [%0], %1;" :: "r"(addr), "l"(v));
}
__device__ __forceinline__ uint32_t smem_u32(const void* p) {
    uint32_t a;
    asm("{ .reg .u64 t; cvta.to.shared.u64 t, %1; cvt.u32.u64 %0, t; }" : "=r"(a) : "l"(p));
    return a;
}

// implicit-LinOSS per-p recurrence coefficients
__device__ __forceinline__ void lin_coefs(const float* __restrict__ A_diag,
                                          const float* __restrict__ steps, int p,
                                          float& m11, float& m12, float& m21, float& m22,
                                          float& f1, float& f2) {
    float A  = fmaxf(A_diag[p], 0.0f);
    float dt = 1.0f / (1.0f + expf(-steps[p]));
    float dt2A = dt * dt * A;
    float S  = 1.0f / (1.0f + dt2A);
    m11 = 1.0f - dt2A * S;
    m12 = -dt * A * S;
    m21 = dt * S;
    m22 = S;
    f1  = m11 * dt;
    f2  = m21 * dt;
}

// ================= kernel A: build fused matrices + power table =================
__global__ __launch_bounds__(256) void kA(const float* __restrict__ W_in,
                                          const float* __restrict__ b_in,
                                          const float* __restrict__ A_diag,
                                          const float* __restrict__ Bmat,
                                          const float* __restrict__ Cmat,
                                          const float* __restrict__ Dvec,
                                          const float* __restrict__ steps,
                                          const float* __restrict__ W_out,
                                          const float* __restrict__ b_out) {
    __shared__ float sbuf[11264];
    const int bid = blockIdx.x, tid = threadIdx.x;

    if (bid < 16) {
        // BW[k][i] = sum_h B_part[k][h] * W_in[h][i]; 16 k-rows per block
        float* Wins = sbuf;                   // [128][64]
        float* Bs   = sbuf + DMODEL * INDIM;  // [16][128]
        for (int i = tid; i < DMODEL * INDIM; i += 256) Wins[i] = W_in[i];
        const int k0 = bid * 16;
        for (int i = tid; i < 16 * DMODEL; i += 256) {
            int kk = i >> 7, h = i & 127;
            int k = k0 + kk, p = k & 127, part = k >> 7;
            Bs[i] = Bmat[(p * DMODEL + h) * 2 + part];
        }
        __syncthreads();
        for (int e = tid; e < 16 * INDIM; e += 256) {
            int kk = e >> 6, i = e & 63;
            float acc = 0.0f;
            #pragma unroll 8
            for (int h = 0; h < DMODEL; h++) acc = fmaf(Bs[kk * DMODEL + h], Wins[h * INDIM + i], acc);
            g_BW[(k0 + kk) * INDIM + i] = acc;
        }
        if (bid == 0) {
            int k = tid, p = k & 127, part = k >> 7;
            float s = 0.0f;
            for (int h = 0; h < DMODEL; h++) s = fmaf(Bmat[(p * DMODEL + h) * 2 + part], b_in[h], s);
            g_BuC[k] = s;
        }
    } else if (bid < 32) {
        // WcT rows: k<128: W_out*C_re ; k<256: -W_out*C_im ; else W_out*diag(D)*W_in
        float* Wos = sbuf;                    // [64][129] padded
        float* Cs  = sbuf + OUTDIM * 129;     // [20][128]
        for (int i = tid; i < OUTDIM * DMODEL; i += 256) {
            int o = i >> 7, h = i & 127;
            Wos[o * 129 + h] = W_out[i];
        }
        const int kb0 = (bid - 16) * 20;
        for (int i = tid; i < 20 * DMODEL; i += 256) {
            int kk = i >> 7, h = i & 127;
            int k = kb0 + kk;
            float v;
            if (k < 128)      v =  Cmat[(h * DMODEL + k) * 2 + 0];
            else if (k < 256) v = -Cmat[(h * DMODEL + (k - 128)) * 2 + 1];
            else              v =  Dvec[h] * W_in[h * INDIM + (k - 256)];
            Cs[i] = v;
        }
        __syncthreads();
        for (int e = tid; e < 20 * OUTDIM; e += 256) {
            int kk = e >> 6, o = e & 63;
            float acc = 0.0f;
            #pragma unroll 8
            for (int h = 0; h < DMODEL; h++) acc = fmaf(Cs[kk * DMODEL + h], Wos[o * 129 + h], acc);
            g_WcT[(kb0 + kk) * OUTDIM + o] = acc;
        }
        if (bid == 16 && tid < OUTDIM) {
            float s = b_out[tid];
            for (int h = 0; h < DMODEL; h++) s = fmaf(W_out[tid * DMODEL + h] * Dvec[h], b_in[h], s);
            g_bias[tid] = s;
        }
    } else {
        // power table Pm[j][p] = M^{j+1}
        if (tid < DMODEL) {
            float m11, m12, m21, m22, f1, f2;
            lin_coefs(A_diag, steps, tid, m11, m12, m21, m22, f1, f2);
            float c11 = m11, c12 = m12, c21 = m21, c22 = m22;
            for (int j = 0; j < TCHUNK; j++) {
                g_Pm[j * DMODEL + tid] = make_float4(c11, c12, c21, c22);
                float n11 = m11 * c11 + m12 * c21;
                float n12 = m11 * c12 + m12 * c22;
                float n21 = m21 * c11 + m22 * c21;
                float n22 = m21 * c12 + m22 * c22;
                c11 = n11; c12 = n12; c21 = n21; c22 = n22;
            }
        }
    }
}

// ================= kernel B: fused Bu-GEMM + chunk-local scan =================
// 128 threads per CTA; 2 CTAs per (b, chunk) each handling 128 chains.
__global__ __launch_bounds__(128) void kB(const float* __restrict__ x,
                                          const float* __restrict__ A_diag,
                                          const float* __restrict__ steps) {
    __shared__ float4 xs4[TCHUNK * INDIM / 4];   // 32KB x tile
    const int b = blockIdx.x >> 6;
    const int c = (blockIdx.x >> 1) & 31;
    const int half = blockIdx.x & 1;
    const int tid = threadIdx.x;

    const float4* xg = (const float4*)(x + (size_t)(b * LSEQ + c * TCHUNK) * INDIM);
    #pragma unroll
    for (int i = 0; i < 16; i++) xs4[tid + i * 128] = xg[tid + i * 128];

    const int k = half * 128 + tid, p = tid;   // p = k & 127 = tid since tid < 128
    float m11, m12, m21, m22, f1, f2;
    lin_coefs(A_diag, steps, p, m11, m12, m21, m22, f1, f2);

    // BW row in registers, pre-packed for f32x2
    unsigned long long bw2[32];
    {
        const float4* br = (const float4*)(g_BW + k * INDIM);
        #pragma unroll
        for (int i = 0; i < 16; i++) {
            float4 v = br[i];
            bw2[2 * i]     = pack2(v.x, v.y);
            bw2[2 * i + 1] = pack2(v.z, v.w);
        }
    }
    const float buc = g_BuC[k];
    __syncthreads();

    const uint32_t xsb = smem_u32(xs4);
    float z = 0.0f, w = 0.0f;
    float* wout = g_w + (size_t)(b * LSEQ + c * TCHUNK) * CHAINS + k;

    #pragma unroll 2
    for (int t = 0; t < TCHUNK; t++) {
        unsigned long long a0 = 0ull, a1 = 0ull, a2 = 0ull, a3 = 0ull;
        const uint32_t base = xsb + t * 256;
        #pragma unroll
        for (int i = 0; i < 8; i++) {
            unsigned long long xA, xB, xC, xD;
            lds_v2u64(xA, xB, base + i * 32);
            lds_v2u64(xC, xD, base + i * 32 + 16);
            a0 = fma2(bw2[4 * i],     xA, a0);
            a1 = fma2(bw2[4 * i + 1], xB, a1);
            a2 = fma2(bw2[4 * i + 2], xC, a2);
            a3 = fma2(bw2[4 * i + 3], xD, a3);
        }
        float2 sf = unpack2(add2(add2(a0, a1), add2(a2, a3)));
        float bu = sf.x + sf.y + buc;
        float nz = fmaf(m11, z, fmaf(m12, w, f1 * bu));
        float nw = fmaf(m21, z, fmaf(m22, w, f2 * bu));
        z = nz; w = nw;
        wout[(size_t)t * CHAINS] = w;
    }
    g_carry[(b * NCHUNK + c) * CHAINS + k] = make_float2(z, w);
}

// ================= kernel C: cross-chunk scan of carries (prefetched) =================
__global__ __launch_bounds__(256) void kC() {
    const int b = blockIdx.x, k = threadIdx.x, p = k & 127;
    const float4 mt = g_Pm[(TCHUNK - 1) * DMODEL + p];   // M^TCHUNK
    float z = 0.0f, w = 0.0f;
    for (int c0 = 0; c0 < NCHUNK; c0 += 8) {
        float2 lc[8];
        #pragma unroll
        for (int j = 0; j < 8; j++)
            lc[j] = g_carry[(b * NCHUNK + c0 + j) * CHAINS + k];
        #pragma unroll
        for (int j = 0; j < 8; j++) {
            g_cin[(b * NCHUNK + c0 + j) * CHAINS + k] = make_float2(z, w);
            float nz = fmaf(mt.x, z, fmaf(mt.y, w, lc[j].x));
            float nw = fmaf(mt.z, z, fmaf(mt.w, w, lc[j].y));
            z = nz; w = nw;
        }
    }
}

// ================= kernel D: carry fixup + fused output GEMM (f32x2) =================
// out[t][o] = sum_k [w_re | w_im | x][t][k] * WcT[k][o] + bias[o],  K=320
// A tile transposed in smem: As_t[kk][row], stride 132 floats (16B aligned).
// B tile duplicated as u64: Bs2[kk][o] = {b,b}.
#define AST_STRIDE 132
__global__ __launch_bounds__(256) void kD(const float* __restrict__ x,
                                          float* __restrict__ out) {
    __shared__ float As_t[32 * AST_STRIDE];                 // 16.9KB
    __shared__ unsigned long long Bs2[32 * 64];             // 16KB
    __shared__ float czs[CHAINS], cws[CHAINS];              // 2KB
    __shared__ unsigned long long biasd[OUTDIM];            // 0.5KB
    const int b = blockIdx.x >> 5, c = blockIdx.x & 31, t0 = c * TCHUNK;
    const int tid = threadIdx.x;

    {
        float2 ci = g_cin[(b * NCHUNK + c) * CHAINS + tid];
        czs[tid] = ci.x; cws[tid] = ci.y;
        if (tid < OUTDIM) {
            float bv = g_bias[tid];
            biasd[tid] = pack2(bv, bv);
        }
    }
    __syncthreads();

    const int tx = tid & 15, ty = tid >> 4;              // compute: 16 col-groups x 16 row-groups
    const int scol = tid & 31, rbase = (tid >> 5) * 16;  // staging: 32 k-cols x 8 row-segments

    // acc[q][cc]: row pair (ty*8+2q, ty*8+2q+1), col tx*4+cc; init = bias
    unsigned long long acc[4][4];
    #pragma unroll
    for (int q = 0; q < 4; q++) {
        #pragma unroll
        for (int cc = 0; cc < 4; cc++) acc[q][cc] = biasd[tx * 4 + cc];
    }

    const uint32_t sA = smem_u32(As_t);
    const uint32_t sB = smem_u32(Bs2);

    for (int ks = 0; ks < 10; ks++) {
        __syncthreads();
        // --- stage B duplicated: Bs2[i] = {WcT[ks*2048+i], same} ---
        #pragma unroll
        for (int q = 0; q < 8; q++) {
            int i = tid + q * 256;
            float v = g_WcT[ks * 2048 + i];
            sts_u64(sB + i * 8, pack2(v, v));
        }
        // --- stage A transposed with carry fixup ---
        if (ks < 8) {
            const int k = ks * 32 + scol;
            const int p = k & 127;
            const float cz = czs[k], cw = cws[k];
            const float* wsrc = g_w + ((size_t)(b * LSEQ) + t0) * CHAINS + k;
            #pragma unroll 4
            for (int j = 0; j < 16; j++) {
                int r = rbase + j;
                float4 pm = g_Pm[r * DMODEL + p];
                As_t[scol * AST_STRIDE + r] =
                    fmaf(pm.z, cz, fmaf(pm.w, cw, wsrc[(size_t)r * CHAINS]));
            }
        } else {
            const int xi = (ks - 8) * 32 + scol;
            const float* xsrc = x + ((size_t)(b * LSEQ) + t0) * INDIM + xi;
            #pragma unroll 4
            for (int j = 0; j < 16; j++) {
                int r = rbase + j;
                As_t[scol * AST_STRIDE + r] = xsrc[(size_t)r * INDIM];
            }
        }
        __syncthreads();
        // --- compute: per kk, 4 LDS + 16 fma2 ---
        #pragma unroll
        for (int kk = 0; kk < 32; kk++) {
            unsigned long long a01, a23, a45, a67, b0, b1, b2, b3;
            const uint32_t abase = sA + kk * (AST_STRIDE * 4) + ty * 32;
            const uint32_t bbase = sB + kk * 512 + tx * 32;
            lds_v2u64(a01, a23, abase);
            lds_v2u64(a45, a67, abase + 16);
            lds_v2u64(b0, b1, bbase);
            lds_v2u64(b2, b3, bbase + 16);
            acc[0][0] = fma2(a01, b0, acc[0][0]);
            acc[0][1] = fma2(a01, b1, acc[0][1]);
            acc[0][2] = fma2(a01, b2, acc[0][2]);
            acc[0][3] = fma2(a01, b3, acc[0][3]);
            acc[1][0] = fma2(a23, b0, acc[1][0]);
            acc[1][1] = fma2(a23, b1, acc[1][1]);
            acc[1][2] = fma2(a23, b2, acc[1][2]);
            acc[1][3] = fma2(a23, b3, acc[1][3]);
            acc[2][0] = fma2(a45, b0, acc[2][0]);
            acc[2][1] = fma2(a45, b1, acc[2][1]);
            acc[2][2] = fma2(a45, b2, acc[2][2]);
            acc[2][3] = fma2(a45, b3, acc[2][3]);
            acc[3][0] = fma2(a67, b0, acc[3][0]);
            acc[3][1] = fma2(a67, b1, acc[3][1]);
            acc[3][2] = fma2(a67, b2, acc[3][2]);
            acc[3][3] = fma2(a67, b3, acc[3][3]);
        }
    }

    // epilogue: unpack row pairs, store float4 per row
    float* og = out + ((size_t)(b * LSEQ) + t0) * OUTDIM + tx * 4;
    #pragma unroll
    for (int q = 0; q < 4; q++) {
        float2 v0 = unpack2(acc[q][0]);
        float2 v1 = unpack2(acc[q][1]);
        float2 v2 = unpack2(acc[q][2]);
        float2 v3 = unpack2(acc[q][3]);
        int row_lo = ty * 8 + 2 * q;
        *(float4*)(og + (size_t)row_lo * OUTDIM) = make_float4(v0.x, v1.x, v2.x, v3.x);
        *(float4*)(og + (size_t)(row_lo + 1) * OUTDIM) = make_float4(v0.y, v1.y, v2.y, v3.y);
    }
}

extern "C" void kernel_launch(void* const* d_in, const int* in_sizes, int n_in,
                              void* d_out, int out_size) {
    const float* x      = (const float*)d_in[0];
    const float* W_in   = (const float*)d_in[1];
    const float* b_in   = (const float*)d_in[2];
    const float* A_diag = (const float*)d_in[3];
    const float* Bmat   = (const float*)d_in[4];
    const float* Cmat   = (const float*)d_in[5];
    const float* Dvec   = (const float*)d_in[6];
    const float* steps  = (const float*)d_in[7];
    const float* W_out  = (const float*)d_in[8];
    const float* b_out  = (const float*)d_in[9];
    float* out = (float*)d_out;

    kA<<<33, 256>>>(W_in, b_in, A_diag, Bmat, Cmat, Dvec, steps, W_out, b_out);
    kB<<<BATCH * NCHUNK * 2, 128>>>(x, A_diag, steps);
    kC<<<BATCH, 256>>>();
    kD<<<BATCH * NCHUNK, 256>>>(x, out);
}

// round 5
// speedup vs baseline: 1.3082x; 1.3082x over previous
#include <cuda_runtime.h>
#include <cstdint>
#include <cstddef>

#define BATCH   16
#define LSEQ    4096
#define INDIM   64
#define DMODEL  128
#define OUTDIM  64
#define TCHUNK  128
#define NCHUNK  32          // LSEQ / TCHUNK
#define CHAINS  256         // 128 p * {re,im}

// ---------------- device scratch (no allocations allowed) ----------------
__device__ float  g_w[(size_t)BATCH * LSEQ * CHAINS];        // local-scan w (67MB)
__device__ float2 g_carry[BATCH * NCHUNK * CHAINS];          // chunk-local final states
__device__ float2 g_cin[BATCH * NCHUNK * CHAINS];            // exclusive cross-chunk prefix
__device__ float  g_BW[CHAINS * INDIM];                      // fused B_part * W_in
__device__ float  g_BuC[CHAINS];                             // B_part * b_in
__device__ float4 g_Pm[TCHUNK * DMODEL];                     // M^{j+1} per p: {m11,m12,m21,m22}
__device__ float  g_WcT[320 * OUTDIM];                       // fused output matrix, [k][o]
__device__ float  g_bias[OUTDIM];

// ---------------- f32x2 / smem helpers ----------------
__device__ __forceinline__ unsigned long long pack2(float lo, float hi) {
    unsigned long long r;
    asm("mov.b64 %0, {%1, %2};" : "=l"(r) : "f"(lo), "f"(hi));
    return r;
}
__device__ __forceinline__ float2 unpack2(unsigned long long v) {
    float lo, hi;
    asm("mov.b64 {%0, %1}, %2;" : "=f"(lo), "=f"(hi) : "l"(v));
    return make_float2(lo, hi);
}
__device__ __forceinline__ unsigned long long fma2(unsigned long long a, unsigned long long b, unsigned long long c) {
    unsigned long long d;
    asm("fma.rn.f32x2 %0, %1, %2, %3;" : "=l"(d) : "l"(a), "l"(b), "l"(c));
    return d;
}
__device__ __forceinline__ unsigned long long add2(unsigned long long a, unsigned long long b) {
    unsigned long long d;
    asm("add.rn.f32x2 %0, %1, %2;" : "=l"(d) : "l"(a), "l"(b));
    return d;
}
__device__ __forceinline__ void lds_v2u64(unsigned long long &a, unsigned long long &b, uint32_t addr) {
    asm volatile("ld.shared.v2.u64 {%0, %1}, [%2];" : "=l"(a), "=l"(b) : "r"(addr));
}
__device__ __forceinline__ void sts_u64(uint32_t addr, unsigned long long v) {
    asm volatile("st.shared.b64 [%0], %1;" :: "r"(addr), "l"(v));
}
__device__ __forceinline__ uint32_t smem_u32(const void* p) {
    uint32_t a;
    asm("{ .reg .u64 t; cvta.to.shared.u64 t, %1; cvt.u32.u64 %0, t; }" : "=r"(a) : "l"(p));
    return a;
}

// implicit-LinOSS per-p recurrence coefficients
__device__ __forceinline__ void lin_coefs(const float* __restrict__ A_diag,
                                          const float* __restrict__ steps, int p,
                                          float& m11, float& m12, float& m21, float& m22,
                                          float& f1, float& f2) {
    float A  = fmaxf(A_diag[p], 0.0f);
    float dt = 1.0f / (1.0f + expf(-steps[p]));
    float dt2A = dt * dt * A;
    float S  = 1.0f / (1.0f + dt2A);
    m11 = 1.0f - dt2A * S;
    m12 = -dt * A * S;
    m21 = dt * S;
    m22 = S;
    f1  = m11 * dt;
    f2  = m21 * dt;
}

// ================= kernel A: build fused matrices + power table =================
__global__ __launch_bounds__(256) void kA(const float* __restrict__ W_in,
                                          const float* __restrict__ b_in,
                                          const float* __restrict__ A_diag,
                                          const float* __restrict__ Bmat,
                                          const float* __restrict__ Cmat,
                                          const float* __restrict__ Dvec,
                                          const float* __restrict__ steps,
                                          const float* __restrict__ W_out,
                                          const float* __restrict__ b_out) {
    __shared__ float sbuf[11264];
    const int bid = blockIdx.x, tid = threadIdx.x;

    if (bid < 16) {
        float* Wins = sbuf;                   // [128][64]
        float* Bs   = sbuf + DMODEL * INDIM;  // [16][128]
        for (int i = tid; i < DMODEL * INDIM; i += 256) Wins[i] = W_in[i];
        const int k0 = bid * 16;
        for (int i = tid; i < 16 * DMODEL; i += 256) {
            int kk = i >> 7, h = i & 127;
            int k = k0 + kk, p = k & 127, part = k >> 7;
            Bs[i] = Bmat[(p * DMODEL + h) * 2 + part];
        }
        __syncthreads();
        for (int e = tid; e < 16 * INDIM; e += 256) {
            int kk = e >> 6, i = e & 63;
            float acc = 0.0f;
            #pragma unroll 8
            for (int h = 0; h < DMODEL; h++) acc = fmaf(Bs[kk * DMODEL + h], Wins[h * INDIM + i], acc);
            g_BW[(k0 + kk) * INDIM + i] = acc;
        }
        if (bid == 0) {
            int k = tid, p = k & 127, part = k >> 7;
            float s = 0.0f;
            for (int h = 0; h < DMODEL; h++) s = fmaf(Bmat[(p * DMODEL + h) * 2 + part], b_in[h], s);
            g_BuC[k] = s;
        }
    } else if (bid < 32) {
        float* Wos = sbuf;                    // [64][129] padded
        float* Cs  = sbuf + OUTDIM * 129;     // [20][128]
        for (int i = tid; i < OUTDIM * DMODEL; i += 256) {
            int o = i >> 7, h = i & 127;
            Wos[o * 129 + h] = W_out[i];
        }
        const int kb0 = (bid - 16) * 20;
        for (int i = tid; i < 20 * DMODEL; i += 256) {
            int kk = i >> 7, h = i & 127;
            int k = kb0 + kk;
            float v;
            if (k < 128)      v =  Cmat[(h * DMODEL + k) * 2 + 0];
            else if (k < 256) v = -Cmat[(h * DMODEL + (k - 128)) * 2 + 1];
            else              v =  Dvec[h] * W_in[h * INDIM + (k - 256)];
            Cs[i] = v;
        }
        __syncthreads();
        for (int e = tid; e < 20 * OUTDIM; e += 256) {
            int kk = e >> 6, o = e & 63;
            float acc = 0.0f;
            #pragma unroll 8
            for (int h = 0; h < DMODEL; h++) acc = fmaf(Cs[kk * DMODEL + h], Wos[o * 129 + h], acc);
            g_WcT[(kb0 + kk) * OUTDIM + o] = acc;
        }
        if (bid == 16 && tid < OUTDIM) {
            float s = b_out[tid];
            for (int h = 0; h < DMODEL; h++) s = fmaf(W_out[tid * DMODEL + h] * Dvec[h], b_in[h], s);
            g_bias[tid] = s;
        }
    } else {
        if (tid < DMODEL) {
            float m11, m12, m21, m22, f1, f2;
            lin_coefs(A_diag, steps, tid, m11, m12, m21, m22, f1, f2);
            float c11 = m11, c12 = m12, c21 = m21, c22 = m22;
            for (int j = 0; j < TCHUNK; j++) {
                g_Pm[j * DMODEL + tid] = make_float4(c11, c12, c21, c22);
                float n11 = m11 * c11 + m12 * c21;
                float n12 = m11 * c12 + m12 * c22;
                float n21 = m21 * c11 + m22 * c21;
                float n22 = m21 * c12 + m22 * c22;
                c11 = n11; c12 = n12; c21 = n21; c22 = n22;
            }
        }
    }
}

// ================= kernel B: fused Bu-GEMM + chunk-local scan =================
// 256 threads, one CTA per (batch, chunk); t-loop unrolled by 2 for ILP.
__global__ __launch_bounds__(256) void kB(const float* __restrict__ x,
                                          const float* __restrict__ A_diag,
                                          const float* __restrict__ steps) {
    __shared__ float4 xs4[TCHUNK * INDIM / 4];   // 32KB x tile
    const int b = blockIdx.x >> 5, c = blockIdx.x & 31;
    const int tid = threadIdx.x;

    const float4* xg = (const float4*)(x + (size_t)(b * LSEQ + c * TCHUNK) * INDIM);
    #pragma unroll
    for (int i = 0; i < 8; i++) xs4[tid + i * 256] = xg[tid + i * 256];

    const int k = tid, p = k & 127;
    float m11, m12, m21, m22, f1, f2;
    lin_coefs(A_diag, steps, p, m11, m12, m21, m22, f1, f2);

    unsigned long long bw2[32];
    {
        const float4* br = (const float4*)(g_BW + k * INDIM);
        #pragma unroll
        for (int i = 0; i < 16; i++) {
            float4 v = br[i];
            bw2[2 * i]     = pack2(v.x, v.y);
            bw2[2 * i + 1] = pack2(v.z, v.w);
        }
    }
    const float buc = g_BuC[k];
    __syncthreads();

    const uint32_t xsb = smem_u32(xs4);
    float z = 0.0f, w = 0.0f;
    float* wout = g_w + (size_t)(b * LSEQ + c * TCHUNK) * CHAINS + k;

    for (int t = 0; t < TCHUNK; t += 2) {
        // two independent dot products in flight
        unsigned long long a0 = 0ull, a1 = 0ull, a2 = 0ull, a3 = 0ull;
        unsigned long long c0 = 0ull, c1 = 0ull, c2 = 0ull, c3 = 0ull;
        const uint32_t baseA = xsb + t * 256;
        const uint32_t baseB = baseA + 256;
        #pragma unroll
        for (int i = 0; i < 8; i++) {
            unsigned long long xA, xB, xC, xD, yA, yB, yC, yD;
            lds_v2u64(xA, xB, baseA + i * 32);
            lds_v2u64(xC, xD, baseA + i * 32 + 16);
            lds_v2u64(yA, yB, baseB + i * 32);
            lds_v2u64(yC, yD, baseB + i * 32 + 16);
            a0 = fma2(bw2[4 * i],     xA, a0);
            a1 = fma2(bw2[4 * i + 1], xB, a1);
            a2 = fma2(bw2[4 * i + 2], xC, a2);
            a3 = fma2(bw2[4 * i + 3], xD, a3);
            c0 = fma2(bw2[4 * i],     yA, c0);
            c1 = fma2(bw2[4 * i + 1], yB, c1);
            c2 = fma2(bw2[4 * i + 2], yC, c2);
            c3 = fma2(bw2[4 * i + 3], yD, c3);
        }
        float2 sf0 = unpack2(add2(add2(a0, a1), add2(a2, a3)));
        float2 sf1 = unpack2(add2(add2(c0, c1), add2(c2, c3)));
        float bu0 = sf0.x + sf0.y + buc;
        float bu1 = sf1.x + sf1.y + buc;
        float nz = fmaf(m11, z, fmaf(m12, w, f1 * bu0));
        float nw = fmaf(m21, z, fmaf(m22, w, f2 * bu0));
        wout[(size_t)t * CHAINS] = nw;
        z = fmaf(m11, nz, fmaf(m12, nw, f1 * bu1));
        w = fmaf(m21, nz, fmaf(m22, nw, f2 * bu1));
        wout[(size_t)(t + 1) * CHAINS] = w;
    }
    g_carry[(b * NCHUNK + c) * CHAINS + k] = make_float2(z, w);
}

// ================= kernel C: cross-chunk scan of carries (prefetched) =================
__global__ __launch_bounds__(256) void kC() {
    const int b = blockIdx.x, k = threadIdx.x, p = k & 127;
    const float4 mt = g_Pm[(TCHUNK - 1) * DMODEL + p];   // M^TCHUNK
    float z = 0.0f, w = 0.0f;
    for (int c0 = 0; c0 < NCHUNK; c0 += 8) {
        float2 lc[8];
        #pragma unroll
        for (int j = 0; j < 8; j++)
            lc[j] = g_carry[(b * NCHUNK + c0 + j) * CHAINS + k];
        #pragma unroll
        for (int j = 0; j < 8; j++) {
            g_cin[(b * NCHUNK + c0 + j) * CHAINS + k] = make_float2(z, w);
            float nz = fmaf(mt.x, z, fmaf(mt.y, w, lc[j].x));
            float nw = fmaf(mt.z, z, fmaf(mt.w, w, lc[j].y));
            z = nz; w = nw;
        }
    }
}

// ================= kernel D: carry fixup + fused output GEMM (f32x2, dup-A) =================
// out[t][o] = sum_k [w_re | w_im | x][t][k] * WcT[k][o] + bias[o],  K=320
// A staged DUPLICATED as u64: Asd[r][kk] = {a,a}  (row-major, 32 kk per row)
//   -> staging stores contiguous (conflict-free), inner loads broadcast,
//      one v2.u64 load fetches {a[kk],a[kk+1]}.
// B staged plain [kk][64]; thread loads its 4 cols as one LDS.128 (contiguous).
__global__ __launch_bounds__(256) void kD(const float* __restrict__ x,
                                          float* __restrict__ out) {
    __shared__ unsigned long long Asd[TCHUNK * 32];   // 32KB
    __shared__ float Bs[32 * 64];                     // 8KB
    __shared__ float czs[CHAINS], cws[CHAINS];        // 2KB
    __shared__ unsigned long long biasp[OUTDIM / 2];  // 256B (col pairs)
    const int b = blockIdx.x >> 5, c = blockIdx.x & 31, t0 = c * TCHUNK;
    const int tid = threadIdx.x;

    {
        float2 ci = g_cin[(b * NCHUNK + c) * CHAINS + tid];
        czs[tid] = ci.x; cws[tid] = ci.y;
        if (tid < OUTDIM / 2)
            biasp[tid] = pack2(g_bias[2 * tid], g_bias[2 * tid + 1]);
    }
    __syncthreads();

    const int tx = tid & 15, ty = tid >> 4;              // compute: 16 col-groups x 16 row-groups
    const int scol = tid & 31, rbase = (tid >> 5) * 16;  // staging: 32 k-cols x 8 row-segments

    // acc[r][cp]: row ty*8+r, col pair (tx*4+2cp, tx*4+2cp+1); init = bias
    unsigned long long acc[8][2];
    {
        unsigned long long b0 = biasp[tx * 2], b1 = biasp[tx * 2 + 1];
        #pragma unroll
        for (int r = 0; r < 8; r++) { acc[r][0] = b0; acc[r][1] = b1; }
    }

    const uint32_t sA = smem_u32(Asd);
    const uint32_t sB = smem_u32(Bs);

    for (int ks = 0; ks < 10; ks++) {
        __syncthreads();
        // stage B plain [32][64]
        #pragma unroll
        for (int it = 0; it < 2; it++) {
            int idx = tid + it * 256;
            ((float4*)Bs)[idx] = ((const float4*)(g_WcT + ks * 32 * OUTDIM))[idx];
        }
        // stage A duplicated with carry fixup
        if (ks < 8) {
            const int k = ks * 32 + scol;
            const int p = k & 127;
            const float cz = czs[k], cw = cws[k];
            const float* wsrc = g_w + ((size_t)(b * LSEQ) + t0) * CHAINS + k;
            #pragma unroll 4
            for (int j = 0; j < 16; j++) {
                int r = rbase + j;
                float4 pm = g_Pm[r * DMODEL + p];
                float v = fmaf(pm.z, cz, fmaf(pm.w, cw, wsrc[(size_t)r * CHAINS]));
                sts_u64(sA + (r * 32 + scol) * 8, pack2(v, v));
            }
        } else {
            const int xi = (ks - 8) * 32 + scol;
            const float* xsrc = x + ((size_t)(b * LSEQ) + t0) * INDIM + xi;
            #pragma unroll 4
            for (int j = 0; j < 16; j++) {
                int r = rbase + j;
                float v = xsrc[(size_t)r * INDIM];
                sts_u64(sA + (r * 32 + scol) * 8, pack2(v, v));
            }
        }
        __syncthreads();
        // compute: per 2 kk: 8 v2.u64 A-loads + 2 LDS.128 B + 32 fma2
        #pragma unroll
        for (int kk = 0; kk < 32; kk += 2) {
            unsigned long long b01a, b23a, b01b, b23b;
            lds_v2u64(b01a, b23a, sB + kk * 256 + tx * 16);
            lds_v2u64(b01b, b23b, sB + (kk + 1) * 256 + tx * 16);
            unsigned long long aA[8], aB[8];
            #pragma unroll
            for (int r = 0; r < 8; r++)
                lds_v2u64(aA[r], aB[r], sA + ((ty * 8 + r) * 32 + kk) * 8);
            #pragma unroll
            for (int r = 0; r < 8; r++) {
                acc[r][0] = fma2(aA[r], b01a, acc[r][0]);
                acc[r][1] = fma2(aA[r], b23a, acc[r][1]);
                acc[r][0] = fma2(aB[r], b01b, acc[r][0]);
                acc[r][1] = fma2(aB[r], b23b, acc[r][1]);
            }
        }
    }

    // epilogue: acc holds (c0,c1),(c2,c3) per row -> one float4 store per row
    float* og = out + ((size_t)(b * LSEQ) + t0) * OUTDIM + tx * 4;
    #pragma unroll
    for (int r = 0; r < 8; r++) {
        float2 v0 = unpack2(acc[r][0]);
        float2 v1 = unpack2(acc[r][1]);
        int row = ty * 8 + r;
        *(float4*)(og + (size_t)row * OUTDIM) = make_float4(v0.x, v0.y, v1.x, v1.y);
    }
}

extern "C" void kernel_launch(void* const* d_in, const int* in_sizes, int n_in,
                              void* d_out, int out_size) {
    const float* x      = (const float*)d_in[0];
    const float* W_in   = (const float*)d_in[1];
    const float* b_in   = (const float*)d_in[2];
    const float* A_diag = (const float*)d_in[3];
    const float* Bmat   = (const float*)d_in[4];
    const float* Cmat   = (const float*)d_in[5];
    const float* Dvec   = (const float*)d_in[6];
    const float* steps  = (const float*)d_in[7];
    const float* W_out  = (const float*)d_in[8];
    const float* b_out  = (const float*)d_in[9];
    float* out = (float*)d_out;

    kA<<<33, 256>>>(W_in, b_in, A_diag, Bmat, Cmat, Dvec, steps, W_out, b_out);
    kB<<<BATCH * NCHUNK, 256>>>(x, A_diag, steps);
    kC<<<BATCH, 256>>>();
    kD<<<BATCH * NCHUNK, 256>>>(x, out);
}